// round 14
// baseline (speedup 1.0000x reference)
#include <cuda_runtime.h>

typedef unsigned long long u64t;

// ---------------- scratch (static device globals — allowed) ----------------
static __device__ __align__(16) float g_Wbig[512 * 128];    // rows 128..511 = [Wk@Wuc1; Wk@Wuc2; Wew@Wuc3]
static __device__ __align__(16) float g_b3[128];            // Web @ Wuc3
static __device__ __align__(16) float g_wqa[128];           // W_q @ a[:128]
static __device__ __align__(16) float g_wka[128];           // W_k @ a[128:]
static __device__ __align__(16) float g_hagg[2][8192][128]; // pre-W_k aggregated neighbor emb

// ---------------- packed f32x2 helpers ----------------
__device__ __forceinline__ u64t pk2(float lo, float hi) {
    u64t r; asm("mov.b64 %0, {%1,%2};" : "=l"(r) : "f"(lo), "f"(hi)); return r;
}
__device__ __forceinline__ void upk2(u64t v, float& lo, float& hi) {
    asm("mov.b64 {%0,%1}, %2;" : "=f"(lo), "=f"(hi) : "l"(v));
}
__device__ __forceinline__ u64t ffma2(u64t a, u64t b, u64t c) {
    u64t d; asm("fma.rn.f32x2 %0, %1, %2, %3;" : "=l"(d) : "l"(a), "l"(b), "l"(c)); return d;
}

// ---------------- cp.async helpers ----------------
__device__ __forceinline__ unsigned smem_u32(const void* p) {
    return (unsigned)__cvta_generic_to_shared(p);
}
__device__ __forceinline__ void cpa16(unsigned d, const void* s) {
    asm volatile("cp.async.cg.shared.global [%0], [%1], 16;" :: "r"(d), "l"(s));
}
#define CP_COMMIT() asm volatile("cp.async.commit_group;" ::: "memory")
#define CP_WAIT(n)  asm volatile("cp.async.wait_group %0;" :: "n"(n) : "memory")
#define HBAR(id)    asm volatile("bar.sync %0, 128;" :: "r"(id) : "memory")

// ---------------- setup_all: blocks 0..383 build Wbig rows; block 384: b3/wqa/wka ----------------
__global__ __launch_bounds__(256) void setup_all(
    const float* __restrict__ Wq, const float* __restrict__ Wk,
    const float* __restrict__ a,  const float* __restrict__ Wew,
    const float* __restrict__ Web, const float* __restrict__ Wuc) {
    const int blk = blockIdx.x;
    const int t = threadIdx.x;
    const int h = t >> 7, j = t & 127;

    if (blk < 384) {
        __shared__ float rowv[128];
        __shared__ float part[128];
        const int seg = (blk >> 7) + 1;      // 1,2,3
        const int i = blk & 127;
        const float* srcrow = (seg == 3 ? Wew : Wk) + i * 128;
        if (h == 0) rowv[j] = srcrow[j];
        __syncthreads();
        float acc = 0.f;
        const int off = seg * 128 + h * 64;
        #pragma unroll 8
        for (int d = 0; d < 64; d++) acc += rowv[h * 64 + d] * Wuc[(off + d) * 128 + j];
        if (h) part[j] = acc;
        __syncthreads();
        if (!h) g_Wbig[(128 + blk) * 128 + j] = acc + part[j];
        return;
    }
    // blk == 384: b3 / wqa / wka, 2-way k-split across h
    __shared__ float pb[128], pq[128], pk[128];
    float b = 0.f, q = 0.f, k2 = 0.f;
    const int d0 = h * 64;
    #pragma unroll 8
    for (int d = d0; d < d0 + 64; d++) {
        b  += Web[d] * Wuc[(384 + d) * 128 + j];
        q  += Wq[j * 128 + d] * a[d];
        k2 += Wk[j * 128 + d] * a[128 + d];
    }
    if (h) { pb[j] = b; pq[j] = q; pk[j] = k2; }
    __syncthreads();
    if (!h) { g_b3[j] = b + pb[j]; g_wqa[j] = q + pq[j]; g_wka[j] = k2 + pk[j]; }
}

// ---------------- attend v5: split-block halves, named barriers, 8 b per block ----------------
// Each half (128 threads) processes one side for 8 consecutive b values, with its own
// double-buffered smem slab. No block-wide syncs -> halves run fully decoupled.
__global__ __launch_bounds__(256) void attend_kernel(
    const float* __restrict__ memb,
    const int* __restrict__ src_idxs, const int* __restrict__ dst_idxs,
    const int* __restrict__ src_nb,   const int* __restrict__ dst_nb) {
    __shared__ float buf[2][2][33 * 132];   // [half][stage][rows]
    __shared__ float sk[2][32];
    __shared__ float sqs[2];

    const int t = threadIdx.x;
    const int h = t >> 7;                // half = side
    const int tt = t & 127;
    const int lane = t & 31;
    const int j = tt >> 2;               // row 0..31
    const int p = tt & 3;                // quarter-row (8 x 16B segments)
    const int b0 = blockIdx.x * 8;

    const int* nbrs = h ? dst_nb   : src_nb;
    const int* idxs = h ? dst_idxs : src_idxs;

    auto gather = [&](int u, int stage) {
        const int b = b0 + u;
        const int nbr = __ldg(&nbrs[b * 32 + j]);
        unsigned dst = smem_u32(&buf[h][stage][j * 132]);
        const char* src = (const char*)(memb + (size_t)nbr * 128);
        #pragma unroll
        for (int s = 0; s < 8; s++)
            cpa16(dst + p * 16 + s * 64, src + p * 16 + s * 64);
        if (tt < 32) {
            const int self = __ldg(&idxs[b]);
            cpa16(smem_u32(&buf[h][stage][32 * 132]) + tt * 16,
                  (const char*)(memb + (size_t)self * 128) + tt * 16);
        }
        CP_COMMIT();
    };

    gather(0, 0);

    #pragma unroll 1
    for (int u = 0; u < 8; u++) {
        const int stage = u & 1;
        HBAR(h + 1);                     // prior reads of stage (u+1)&1 complete
        if (u + 1 < 8) { gather(u + 1, stage ^ 1); CP_WAIT(1); }
        else           { CP_WAIT(0); }
        HBAR(h + 1);                     // stage u data visible to all half-threads

        const int b = b0 + u;

        // sq = self . wqa (warp 0 of half)
        if (tt < 32) {
            float4 v = *(const float4*)&buf[h][stage][32 * 132 + lane * 4];
            float4 w = ((const float4*)g_wqa)[lane];
            float s = v.x * w.x + v.y * w.y + v.z * w.z + v.w * w.w;
            #pragma unroll
            for (int o = 16; o; o >>= 1) s += __shfl_xor_sync(0xffffffffu, s, o);
            if (lane == 0) sqs[h] = s;
        }

        // sk[j] = row_j . wka : 4 threads per row
        {
            float part = 0.f;
            #pragma unroll
            for (int s = 0; s < 8; s++) {
                const int f = p * 8 + s;     // float4 index 0..31
                float4 v = *(const float4*)&buf[h][stage][j * 132 + f * 4];
                float4 w = ((const float4*)g_wka)[f];
                part += v.x * w.x + v.y * w.y + v.z * w.z + v.w * w.w;
            }
            part += __shfl_xor_sync(0xffffffffu, part, 1);
            part += __shfl_xor_sync(0xffffffffu, part, 2);
            if (p == 0) sk[h][j] = part;
        }
        HBAR(h + 1);                     // sk + sqs visible

        // per-warp redundant softmax: lane holds attn[lane]
        float attn_l;
        {
            float s = sqs[h] + sk[h][lane];
            s = s > 0.f ? s : 0.2f * s;
            float m = s;
            #pragma unroll
            for (int o = 16; o; o >>= 1) m = fmaxf(m, __shfl_xor_sync(0xffffffffu, m, o));
            float e = __expf(s - m);
            float sum = e;
            #pragma unroll
            for (int o = 16; o; o >>= 1) sum += __shfl_xor_sync(0xffffffffu, sum, o);
            attn_l = e / sum;
        }

        // weighted sum: all 128 half-threads, one column each
        {
            float acc = 0.f;
            #pragma unroll
            for (int jj = 0; jj < 32; jj++)
                acc += __shfl_sync(0xffffffffu, attn_l, jj) * buf[h][stage][jj * 132 + tt];
            g_hagg[h][b][tt] = acc;
        }
    }
}

// ---------------- fused MLP: FR=64, 8r x 4c tile, 3-stage weight pipeline ----------------
#define FR 64
#define XSTR 516
#define XS_FLOATS (FR * XSTR)          // 33024
#define WCHUNK_FLOATS (64 * 128)       // 8192
#define FINAL_SMEM_BYTES ((XS_FLOATS + 3 * WCHUNK_FLOATS) * 4)   // 230400

__device__ __forceinline__ void prefetchW64(const float* __restrict__ Wg, float* dstbuf, int t) {
    unsigned dbase = smem_u32(dstbuf);
    #pragma unroll
    for (int i = 0; i < 8; i++) {
        int f4 = i * 256 + t;
        cpa16(dbase + f4 * 16, (const char*)Wg + f4 * 16);
    }
}

__device__ __forceinline__ void prefetchWc2(const float* __restrict__ Wg, float* dstbuf, int t) {
    unsigned dbase = smem_u32(dstbuf);
    #pragma unroll
    for (int i = 0; i < 8; i++) {
        int f4 = i * 256 + t;                 // need 1920 float4s
        if (f4 < 1920) cpa16(dbase + f4 * 16, (const char*)Wg + f4 * 16);
    }
}

// 64-k chunk: thread computes 8 rows x 4 cols; A loaded as float4 over k.
__device__ __forceinline__ void mac_chunk64(const float* __restrict__ A, int astride,
                                            const float* __restrict__ Wb, int c0,
                                            u64t acc[16]) {
    #pragma unroll 2
    for (int k4 = 0; k4 < 16; k4++) {
        const float* wp = Wb + k4 * 4 * 128 + c0;
        ulonglong2 w0 = *(const ulonglong2*)(wp);
        ulonglong2 w1 = *(const ulonglong2*)(wp + 128);
        ulonglong2 w2 = *(const ulonglong2*)(wp + 256);
        ulonglong2 w3 = *(const ulonglong2*)(wp + 384);
        #pragma unroll
        for (int i = 0; i < 8; i++) {
            float4 av = *(const float4*)(A + i * astride + k4 * 4);
            u64t vx = pk2(av.x, av.x), vy = pk2(av.y, av.y);
            u64t vz = pk2(av.z, av.z), vw = pk2(av.w, av.w);
            acc[i * 2]     = ffma2(vx, w0.x, acc[i * 2]);
            acc[i * 2 + 1] = ffma2(vx, w0.y, acc[i * 2 + 1]);
            acc[i * 2]     = ffma2(vy, w1.x, acc[i * 2]);
            acc[i * 2 + 1] = ffma2(vy, w1.y, acc[i * 2 + 1]);
            acc[i * 2]     = ffma2(vz, w2.x, acc[i * 2]);
            acc[i * 2 + 1] = ffma2(vz, w2.y, acc[i * 2 + 1]);
            acc[i * 2]     = ffma2(vw, w3.x, acc[i * 2]);
            acc[i * 2 + 1] = ffma2(vw, w3.y, acc[i * 2 + 1]);
        }
    }
}

__global__ __launch_bounds__(256) void final_kernel(
    const float* __restrict__ memb, const float* __restrict__ edge_feat,
    const float* __restrict__ Wuc,  const float* __restrict__ Wc1,
    const float* __restrict__ Wc2,
    const int* __restrict__ src_idxs, const int* __restrict__ dst_idxs,
    const int* __restrict__ edge_idxs, float* __restrict__ out) {
    extern __shared__ float sm[];
    float* Xs   = sm;                      // 64 x 516 (X; later MSG @0, TB @8448)
    float* Wbuf = sm + XS_FLOATS;          // 3 x (64 x 128)

    const int t = threadIdx.x;
    const int side = blockIdx.y;
    const int b0 = blockIdx.x * FR;
    const int* idxs = side ? dst_idxs : src_idxs;

    // prologue: chunks 0,1 in flight
    prefetchW64(Wuc, Wbuf, t);                        CP_COMMIT();
    prefetchW64(Wuc + WCHUNK_FLOATS, Wbuf + WCHUNK_FLOATS, t); CP_COMMIT();

    // ---- gather X = [self | h_self | h_other | edge] : 64 x 512 ----
    {
        const int r = t >> 2, q = t & 3;
        const int b = b0 + r;
        const float4* s0 = (const float4*)(memb + (size_t)idxs[b] * 128);
        const float4* s1 = (const float4*)(&g_hagg[side][b][0]);
        const float4* s2 = (const float4*)(&g_hagg[side ^ 1][b][0]);
        const float4* s3 = (const float4*)(edge_feat + (size_t)edge_idxs[b] * 128);
        float4* d = (float4*)(Xs + r * XSTR);
        #pragma unroll
        for (int i = 0; i < 8; i++) d[q * 8 + i]      = s0[q * 8 + i];
        #pragma unroll
        for (int i = 0; i < 8; i++) d[32 + q * 8 + i] = s1[q * 8 + i];
        #pragma unroll
        for (int i = 0; i < 8; i++) d[64 + q * 8 + i] = s2[q * 8 + i];
        #pragma unroll
        for (int i = 0; i < 8; i++) d[96 + q * 8 + i] = s3[q * 8 + i];
    }

    const int rgg = t >> 5;                // 0..7: rows rgg*8 .. rgg*8+7
    const int cgg = t & 31;                // warp-uniform rgg -> A loads broadcast
    const int c0 = cgg * 4;
    const int r0 = rgg * 8;

    // ---- phase 2: MSG = relu(X @ Wbig + b3), k = 512 in 8 chunks, 1 sync/chunk ----
    u64t acc[16];
    {
        u64t bv0 = *(const u64t*)(g_b3 + c0);
        u64t bv1 = *(const u64t*)(g_b3 + c0 + 2);
        #pragma unroll
        for (int i = 0; i < 8; i++) { acc[i * 2] = bv0; acc[i * 2 + 1] = bv1; }
    }

    #pragma unroll 1
    for (int kc = 0; kc < 8; kc++) {
        if (kc < 7) { CP_WAIT(1); } else { CP_WAIT(0); }
        __syncthreads();   // stage kc%3 published; stage (kc+2)%3 free; (kc=0) X visible
        if (kc + 2 < 8) {
            const float* src = (kc + 2 < 2) ? (Wuc + (kc + 2) * WCHUNK_FLOATS)
                                            : (g_Wbig + (kc + 2) * WCHUNK_FLOATS);
            prefetchW64(src, Wbuf + ((kc + 2) % 3) * WCHUNK_FLOATS, t);
            CP_COMMIT();
        }
        mac_chunk64(Xs + r0 * XSTR + kc * 64, XSTR,
                    Wbuf + (kc % 3) * WCHUNK_FLOATS, c0, acc);
    }
    __syncthreads();                       // all mac(7) done before MSG overwrites X

    // write MSG (stride 132) into Xs[0..8448)
    float* MSG = Xs;
    #pragma unroll
    for (int i = 0; i < 8; i++) {
        float l0, h0, l1, h1;
        upk2(acc[i * 2], l0, h0);
        upk2(acc[i * 2 + 1], l1, h1);
        *(float4*)(MSG + (r0 + i) * 132 + c0) =
            make_float4(fmaxf(l0, 0.f), fmaxf(h0, 0.f), fmaxf(l1, 0.f), fmaxf(h1, 0.f));
    }

    // ---- phase 3 prologue: Wc1 chunks -> stages 0,1; Wc2 -> stage 2 ----
    prefetchW64(Wc1, Wbuf, t);                                  CP_COMMIT();
    prefetchW64(Wc1 + WCHUNK_FLOATS, Wbuf + WCHUNK_FLOATS, t);  CP_COMMIT();
    prefetchWc2(Wc2, Wbuf + 2 * WCHUNK_FLOATS, t);              CP_COMMIT();

    u64t acc2[16];
    #pragma unroll
    for (int pz = 0; pz < 16; pz++) acc2[pz] = 0ull;

    CP_WAIT(2);
    __syncthreads();                       // Wc1 chunk0 + MSG visible
    mac_chunk64(MSG + r0 * 132, 132, Wbuf, c0, acc2);
    CP_WAIT(1);
    __syncthreads();                       // Wc1 chunk1 visible
    mac_chunk64(MSG + r0 * 132 + 64, 132, Wbuf + WCHUNK_FLOATS, c0, acc2);

    float* TB = Xs + FR * 132;             // floats 8448..16896 (disjoint from MSG)
    #pragma unroll
    for (int i = 0; i < 8; i++) {
        float l0, h0, l1, h1;
        upk2(acc2[i * 2], l0, h0);
        upk2(acc2[i * 2 + 1], l1, h1);
        *(float4*)(TB + (r0 + i) * 132 + c0) =
            make_float4(fmaxf(l0, 0.f), fmaxf(h0, 0.f), fmaxf(l1, 0.f), fmaxf(h1, 0.f));
    }

    CP_WAIT(0);
    __syncthreads();                       // TB + Wc2 visible

    // ---- phase 4: logits = TB @ Wc2 (128 x 60) from stage 2 ----
    const float* Wc2s = Wbuf + 2 * WCHUNK_FLOATS;
    const int c2 = cgg * 2;                // cgg 30,31 -> cols >= 60: inactive
    if (c2 < 60) {
        u64t a4[8];
        #pragma unroll
        for (int pz = 0; pz < 8; pz++) a4[pz] = 0ull;
        const float* A = TB + r0 * 132;
        #pragma unroll 2
        for (int k4 = 0; k4 < 32; k4++) {
            u64t w0 = *(const u64t*)(Wc2s + (k4 * 4)     * 60 + c2);
            u64t w1 = *(const u64t*)(Wc2s + (k4 * 4 + 1) * 60 + c2);
            u64t w2 = *(const u64t*)(Wc2s + (k4 * 4 + 2) * 60 + c2);
            u64t w3 = *(const u64t*)(Wc2s + (k4 * 4 + 3) * 60 + c2);
            #pragma unroll
            for (int i = 0; i < 8; i++) {
                float4 av = *(const float4*)(A + i * 132 + k4 * 4);
                a4[i] = ffma2(pk2(av.x, av.x), w0, a4[i]);
                a4[i] = ffma2(pk2(av.y, av.y), w1, a4[i]);
                a4[i] = ffma2(pk2(av.z, av.z), w2, a4[i]);
                a4[i] = ffma2(pk2(av.w, av.w), w3, a4[i]);
            }
        }
        #pragma unroll
        for (int i = 0; i < 8; i++) {
            float lo, hi;
            upk2(a4[i], lo, hi);
            float* o = out + ((size_t)side * 8192 + b0 + r0 + i) * 60 + c2;
            o[0] = lo; o[1] = hi;
        }
    }
}

// ---------------- launch ----------------
extern "C" void kernel_launch(void* const* d_in, const int* in_sizes, int n_in,
                              void* d_out, int out_size) {
    (void)in_sizes; (void)n_in; (void)out_size;
    const float* memb      = (const float*)d_in[0];
    const float* edge_feat = (const float*)d_in[1];
    const float* Wq        = (const float*)d_in[2];
    const float* Wk        = (const float*)d_in[3];
    const float* a         = (const float*)d_in[4];
    const float* Wew       = (const float*)d_in[5];
    const float* Web       = (const float*)d_in[6];
    const float* Wuc       = (const float*)d_in[7];
    const float* Wc1       = (const float*)d_in[8];
    const float* Wc2       = (const float*)d_in[9];
    const int* src_idxs    = (const int*)d_in[10];
    const int* dst_idxs    = (const int*)d_in[11];
    const int* edge_idxs   = (const int*)d_in[12];
    const int* src_nb      = (const int*)d_in[13];
    const int* dst_nb      = (const int*)d_in[14];
    float* out = (float*)d_out;

    setup_all<<<385, 256>>>(Wq, Wk, a, Wew, Web, Wuc);
    attend_kernel<<<1024, 256>>>(memb, src_idxs, dst_idxs, src_nb, dst_nb);
    cudaFuncSetAttribute(final_kernel, cudaFuncAttributeMaxDynamicSharedMemorySize,
                         FINAL_SMEM_BYTES);
    final_kernel<<<dim3(128, 2), 256, FINAL_SMEM_BYTES>>>(memb, edge_feat, Wuc, Wc1, Wc2,
                                                          src_idxs, dst_idxs, edge_idxs, out);
}

// round 15
// speedup vs baseline: 1.2216x; 1.2216x over previous
#include <cuda_runtime.h>

typedef unsigned long long u64t;

// ---------------- scratch (static device globals — allowed) ----------------
static __device__ __align__(16) float g_Wbig[512 * 128];    // rows 128..511 = [Wk@Wuc1; Wk@Wuc2; Wew@Wuc3]
static __device__ __align__(16) float g_b3[128];            // Web @ Wuc3
static __device__ __align__(16) float g_wqa[128];           // W_q @ a[:128]
static __device__ __align__(16) float g_wka[128];           // W_k @ a[128:]
static __device__ __align__(16) float g_hagg[2][8192][128]; // pre-W_k aggregated neighbor emb

// ---------------- packed f32x2 helpers ----------------
__device__ __forceinline__ u64t pk2(float lo, float hi) {
    u64t r; asm("mov.b64 %0, {%1,%2};" : "=l"(r) : "f"(lo), "f"(hi)); return r;
}
__device__ __forceinline__ void upk2(u64t v, float& lo, float& hi) {
    asm("mov.b64 {%0,%1}, %2;" : "=f"(lo), "=f"(hi) : "l"(v));
}
__device__ __forceinline__ u64t ffma2(u64t a, u64t b, u64t c) {
    u64t d; asm("fma.rn.f32x2 %0, %1, %2, %3;" : "=l"(d) : "l"(a), "l"(b), "l"(c)); return d;
}

// ---------------- cp.async helpers ----------------
__device__ __forceinline__ unsigned smem_u32(const void* p) {
    return (unsigned)__cvta_generic_to_shared(p);
}
__device__ __forceinline__ void cpa16(unsigned d, const void* s) {
    asm volatile("cp.async.cg.shared.global [%0], [%1], 16;" :: "r"(d), "l"(s));
}
#define CP_COMMIT() asm volatile("cp.async.commit_group;" ::: "memory")
#define CP_WAIT(n)  asm volatile("cp.async.wait_group %0;" :: "n"(n) : "memory")

// ---------------- setup_small: b3 / wqa / wka (1 block) ----------------
__global__ __launch_bounds__(128) void setup_small(
    const float* __restrict__ Wq, const float* __restrict__ Wk,
    const float* __restrict__ a,  const float* __restrict__ Web,
    const float* __restrict__ Wuc) {
    const int j = threadIdx.x;
    float b = 0.f, q = 0.f, k2 = 0.f;
    #pragma unroll 8
    for (int d = 0; d < 128; d++) {
        b  += Web[d] * Wuc[(384 + d) * 128 + j];
        q  += Wq[j * 128 + d] * a[d];
        k2 += Wk[j * 128 + d] * a[128 + d];
    }
    g_b3[j] = b; g_wqa[j] = q; g_wka[j] = k2;
}

// ---------------- setup_wbig: rows 128..511 of Wbig, 2-way k-split ----------------
__global__ __launch_bounds__(256) void setup_wbig(
    const float* __restrict__ Wk, const float* __restrict__ Wew,
    const float* __restrict__ Wuc) {
    __shared__ float rowv[128];
    __shared__ float part[128];
    const int blk = blockIdx.x;          // 0..383
    const int t = threadIdx.x;
    const int h = t >> 7, j = t & 127;
    const int seg = (blk >> 7) + 1;      // 1,2,3
    const int i = blk & 127;
    const float* srcrow = (seg == 3 ? Wew : Wk) + i * 128;
    if (h == 0) rowv[j] = srcrow[j];
    __syncthreads();
    float acc = 0.f;
    const int off = seg * 128 + h * 64;
    #pragma unroll 8
    for (int d = 0; d < 64; d++) acc += rowv[h * 64 + d] * Wuc[(off + d) * 128 + j];
    if (h) part[j] = acc;
    __syncthreads();
    if (!h) g_Wbig[(128 + blk) * 128 + j] = acc + part[j];
}

// ---------------- attend v4: 4 b per block, pipelined, shfl softmax ----------------
__global__ __launch_bounds__(256) void attend_kernel(
    const float* __restrict__ memb,
    const int* __restrict__ src_idxs, const int* __restrict__ dst_idxs,
    const int* __restrict__ src_nb,   const int* __restrict__ dst_nb) {
    __shared__ float buf[2][33 * 132];
    __shared__ float sk[32];
    __shared__ float sqs;

    const int t = threadIdx.x;
    const int b0 = blockIdx.x * 4;
    const int j = t >> 3;                // row 0..31
    const int p = t & 7;                 // 16B segment group within row
    const int lane = t & 31;

    auto gather = [&](int u, int stage) {
        const int b = b0 + (u >> 1);
        const int side = u & 1;
        const int* nbrs = side ? dst_nb : src_nb;
        const int nbr = __ldg(&nbrs[b * 32 + j]);
        unsigned dst = smem_u32(&buf[stage][j * 132]);
        const char* src = (const char*)(memb + (size_t)nbr * 128);
        #pragma unroll
        for (int s = 0; s < 4; s++)
            cpa16(dst + p * 16 + s * 128, src + p * 16 + s * 128);
        if (t < 32) {
            const int* idxs = side ? dst_idxs : src_idxs;
            const int self = __ldg(&idxs[b]);
            cpa16(smem_u32(&buf[stage][32 * 132]) + t * 16,
                  (const char*)(memb + (size_t)self * 128) + t * 16);
        }
        CP_COMMIT();
    };

    gather(0, 0);

    #pragma unroll 1
    for (int u = 0; u < 8; u++) {
        __syncthreads();                 // all reads of buf[(u+1)&1] from iter u-1 done
        if (u + 1 < 8) { gather(u + 1, (u + 1) & 1); CP_WAIT(1); }
        else           { CP_WAIT(0); }
        __syncthreads();                 // stage u fully visible

        const int stage = u & 1;
        const int b = b0 + (u >> 1);
        const int side = u & 1;

        // sq = self . wqa (warp 1)
        if (t >= 32 && t < 64) {
            float4 v = *(const float4*)&buf[stage][32 * 132 + lane * 4];
            float4 w = ((const float4*)g_wqa)[lane];
            float s = v.x * w.x + v.y * w.y + v.z * w.z + v.w * w.w;
            #pragma unroll
            for (int o = 16; o; o >>= 1) s += __shfl_xor_sync(0xffffffffu, s, o);
            if (lane == 0) sqs = s;
        }

        // sk[j] = row_j . wka : 8 threads per row
        {
            float part = 0.f;
            #pragma unroll
            for (int s = 0; s < 4; s++) {
                const int f = p + s * 8;
                float4 v = *(const float4*)&buf[stage][j * 132 + f * 4];
                float4 w = ((const float4*)g_wka)[f];
                part += v.x * w.x + v.y * w.y + v.z * w.z + v.w * w.w;
            }
            part += __shfl_xor_sync(0xffffffffu, part, 1);
            part += __shfl_xor_sync(0xffffffffu, part, 2);
            part += __shfl_xor_sync(0xffffffffu, part, 4);
            if (p == 0) sk[j] = part;
        }
        __syncthreads();                 // sk + sqs visible

        // per-warp redundant softmax: lane holds attn[lane] in register
        float attn_l;
        {
            float s = sqs + sk[lane];
            s = s > 0.f ? s : 0.2f * s;
            float m = s;
            #pragma unroll
            for (int o = 16; o; o >>= 1) m = fmaxf(m, __shfl_xor_sync(0xffffffffu, m, o));
            float e = __expf(s - m);
            float sum = e;
            #pragma unroll
            for (int o = 16; o; o >>= 1) sum += __shfl_xor_sync(0xffffffffu, sum, o);
            attn_l = e / sum;
        }

        // weighted sum: threads 0..127, one column each; attn via shfl broadcast
        if (t < 128) {
            float acc = 0.f;
            #pragma unroll
            for (int jj = 0; jj < 32; jj++)
                acc += __shfl_sync(0xffffffffu, attn_l, jj) * buf[stage][jj * 132 + t];
            g_hagg[side][b][t] = acc;
        }
    }
}

// ---------------- fused MLP: FR=64, 8r x 4c tile, 3-stage smem + register-pipelined weights ----------------
#define FR 64
#define XSTR 516
#define XS_FLOATS (FR * XSTR)          // 33024
#define WCHUNK_FLOATS (64 * 128)       // 8192
#define FINAL_SMEM_BYTES ((XS_FLOATS + 3 * WCHUNK_FLOATS) * 4)   // 230400

__device__ __forceinline__ void prefetchW64(const float* __restrict__ Wg, float* dstbuf, int t) {
    unsigned dbase = smem_u32(dstbuf);
    #pragma unroll
    for (int i = 0; i < 8; i++) {
        int f4 = i * 256 + t;
        cpa16(dbase + f4 * 16, (const char*)Wg + f4 * 16);
    }
}

__device__ __forceinline__ void prefetchWc2(const float* __restrict__ Wg, float* dstbuf, int t) {
    unsigned dbase = smem_u32(dstbuf);
    #pragma unroll
    for (int i = 0; i < 8; i++) {
        int f4 = i * 256 + t;                 // need 1920 float4s
        if (f4 < 1920) cpa16(dbase + f4 * 16, (const char*)Wg + f4 * 16);
    }
}

__device__ __forceinline__ void loadW4(const float* __restrict__ wp, ulonglong2 w[4]) {
    w[0] = *(const ulonglong2*)(wp);
    w[1] = *(const ulonglong2*)(wp + 128);
    w[2] = *(const ulonglong2*)(wp + 256);
    w[3] = *(const ulonglong2*)(wp + 384);
}

__device__ __forceinline__ void compute4(const float* __restrict__ A, int astride, int koff,
                                         const ulonglong2 w[4], u64t acc[16]) {
    #pragma unroll
    for (int i = 0; i < 8; i++) {
        float4 a = *(const float4*)(A + i * astride + koff);
        u64t vx = pk2(a.x, a.x), vy = pk2(a.y, a.y);
        u64t vz = pk2(a.z, a.z), vw = pk2(a.w, a.w);
        acc[i * 2]     = ffma2(vx, w[0].x, acc[i * 2]);
        acc[i * 2 + 1] = ffma2(vx, w[0].y, acc[i * 2 + 1]);
        acc[i * 2]     = ffma2(vy, w[1].x, acc[i * 2]);
        acc[i * 2 + 1] = ffma2(vy, w[1].y, acc[i * 2 + 1]);
        acc[i * 2]     = ffma2(vz, w[2].x, acc[i * 2]);
        acc[i * 2 + 1] = ffma2(vz, w[2].y, acc[i * 2 + 1]);
        acc[i * 2]     = ffma2(vw, w[3].x, acc[i * 2]);
        acc[i * 2 + 1] = ffma2(vw, w[3].y, acc[i * 2 + 1]);
    }
}

// 64-k chunk, weights register-ping-pong pipelined one k4-group ahead.
__device__ __forceinline__ void mac_chunk64(const float* __restrict__ A, int astride,
                                            const float* __restrict__ Wb, int c0,
                                            u64t acc[16]) {
    ulonglong2 wA[4], wB[4];
    loadW4(Wb + c0, wA);
    #pragma unroll
    for (int k4 = 0; k4 < 16; k4 += 2) {
        loadW4(Wb + (k4 + 1) * 512 + c0, wB);
        compute4(A, astride, k4 * 4, wA, acc);
        if (k4 + 2 < 16) loadW4(Wb + (k4 + 2) * 512 + c0, wA);
        compute4(A, astride, (k4 + 1) * 4, wB, acc);
    }
}

__global__ __launch_bounds__(256) void final_kernel(
    const float* __restrict__ memb, const float* __restrict__ edge_feat,
    const float* __restrict__ Wuc,  const float* __restrict__ Wc1,
    const float* __restrict__ Wc2,
    const int* __restrict__ src_idxs, const int* __restrict__ dst_idxs,
    const int* __restrict__ edge_idxs, float* __restrict__ out) {
    extern __shared__ float sm[];
    float* Xs   = sm;                      // 64 x 516 (X; later MSG @0, TB @8448)
    float* Wbuf = sm + XS_FLOATS;          // 3 x (64 x 128)

    const int t = threadIdx.x;
    const int side = blockIdx.y;
    const int b0 = blockIdx.x * FR;
    const int* idxs = side ? dst_idxs : src_idxs;

    // prologue: chunks 0,1 in flight
    prefetchW64(Wuc, Wbuf, t);                        CP_COMMIT();
    prefetchW64(Wuc + WCHUNK_FLOATS, Wbuf + WCHUNK_FLOATS, t); CP_COMMIT();

    // ---- gather X = [self | h_self | h_other | edge] : 64 x 512 ----
    {
        const int r = t >> 2, q = t & 3;
        const int b = b0 + r;
        const float4* s0 = (const float4*)(memb + (size_t)idxs[b] * 128);
        const float4* s1 = (const float4*)(&g_hagg[side][b][0]);
        const float4* s2 = (const float4*)(&g_hagg[side ^ 1][b][0]);
        const float4* s3 = (const float4*)(edge_feat + (size_t)edge_idxs[b] * 128);
        float4* d = (float4*)(Xs + r * XSTR);
        #pragma unroll
        for (int i = 0; i < 8; i++) d[q * 8 + i]      = s0[q * 8 + i];
        #pragma unroll
        for (int i = 0; i < 8; i++) d[32 + q * 8 + i] = s1[q * 8 + i];
        #pragma unroll
        for (int i = 0; i < 8; i++) d[64 + q * 8 + i] = s2[q * 8 + i];
        #pragma unroll
        for (int i = 0; i < 8; i++) d[96 + q * 8 + i] = s3[q * 8 + i];
    }

    const int rgg = t >> 5;                // 0..7: rows rgg*8 .. rgg*8+7
    const int cgg = t & 31;                // warp-uniform rgg -> A loads broadcast
    const int c0 = cgg * 4;
    const int r0 = rgg * 8;

    // ---- phase 2: MSG = relu(X @ Wbig + b3), k = 512 in 8 chunks, 1 sync/chunk ----
    u64t acc[16];
    {
        u64t bv0 = *(const u64t*)(g_b3 + c0);
        u64t bv1 = *(const u64t*)(g_b3 + c0 + 2);
        #pragma unroll
        for (int i = 0; i < 8; i++) { acc[i * 2] = bv0; acc[i * 2 + 1] = bv1; }
    }

    #pragma unroll 1
    for (int kc = 0; kc < 8; kc++) {
        if (kc < 7) { CP_WAIT(1); } else { CP_WAIT(0); }
        __syncthreads();   // stage kc%3 published; stage (kc+2)%3 free; (kc=0) X visible
        if (kc + 2 < 8) {
            const float* src = (kc + 2 < 2) ? (Wuc + (kc + 2) * WCHUNK_FLOATS)
                                            : (g_Wbig + (kc + 2) * WCHUNK_FLOATS);
            prefetchW64(src, Wbuf + ((kc + 2) % 3) * WCHUNK_FLOATS, t);
            CP_COMMIT();
        }
        mac_chunk64(Xs + r0 * XSTR + kc * 64, XSTR,
                    Wbuf + (kc % 3) * WCHUNK_FLOATS, c0, acc);
    }
    __syncthreads();                       // all mac(7) done before MSG overwrites X

    // write MSG (stride 132) into Xs[0..8448)
    float* MSG = Xs;
    #pragma unroll
    for (int i = 0; i < 8; i++) {
        float l0, h0, l1, h1;
        upk2(acc[i * 2], l0, h0);
        upk2(acc[i * 2 + 1], l1, h1);
        *(float4*)(MSG + (r0 + i) * 132 + c0) =
            make_float4(fmaxf(l0, 0.f), fmaxf(h0, 0.f), fmaxf(l1, 0.f), fmaxf(h1, 0.f));
    }

    // ---- phase 3 prologue: Wc1 chunks -> stages 0,1; Wc2 -> stage 2 ----
    prefetchW64(Wc1, Wbuf, t);                                  CP_COMMIT();
    prefetchW64(Wc1 + WCHUNK_FLOATS, Wbuf + WCHUNK_FLOATS, t);  CP_COMMIT();
    prefetchWc2(Wc2, Wbuf + 2 * WCHUNK_FLOATS, t);              CP_COMMIT();

    u64t acc2[16];
    #pragma unroll
    for (int pz = 0; pz < 16; pz++) acc2[pz] = 0ull;

    CP_WAIT(2);
    __syncthreads();                       // Wc1 chunk0 + MSG visible
    mac_chunk64(MSG + r0 * 132, 132, Wbuf, c0, acc2);
    CP_WAIT(1);
    __syncthreads();                       // Wc1 chunk1 visible
    mac_chunk64(MSG + r0 * 132 + 64, 132, Wbuf + WCHUNK_FLOATS, c0, acc2);

    float* TB = Xs + FR * 132;             // floats 8448..16896 (disjoint from MSG)
    #pragma unroll
    for (int i = 0; i < 8; i++) {
        float l0, h0, l1, h1;
        upk2(acc2[i * 2], l0, h0);
        upk2(acc2[i * 2 + 1], l1, h1);
        *(float4*)(TB + (r0 + i) * 132 + c0) =
            make_float4(fmaxf(l0, 0.f), fmaxf(h0, 0.f), fmaxf(l1, 0.f), fmaxf(h1, 0.f));
    }

    CP_WAIT(0);
    __syncthreads();                       // TB + Wc2 visible

    // ---- phase 4: logits = TB @ Wc2 (128 x 60) from stage 2 ----
    const float* Wc2s = Wbuf + 2 * WCHUNK_FLOATS;
    const int c2 = cgg * 2;                // cgg 30,31 -> cols >= 60: inactive
    if (c2 < 60) {
        u64t a4[8];
        #pragma unroll
        for (int pz = 0; pz < 8; pz++) a4[pz] = 0ull;
        const float* A = TB + r0 * 132;
        #pragma unroll 2
        for (int k4 = 0; k4 < 32; k4++) {
            u64t w0 = *(const u64t*)(Wc2s + (k4 * 4)     * 60 + c2);
            u64t w1 = *(const u64t*)(Wc2s + (k4 * 4 + 1) * 60 + c2);
            u64t w2 = *(const u64t*)(Wc2s + (k4 * 4 + 2) * 60 + c2);
            u64t w3 = *(const u64t*)(Wc2s + (k4 * 4 + 3) * 60 + c2);
            #pragma unroll
            for (int i = 0; i < 8; i++) {
                float4 av = *(const float4*)(A + i * 132 + k4 * 4);
                a4[i] = ffma2(pk2(av.x, av.x), w0, a4[i]);
                a4[i] = ffma2(pk2(av.y, av.y), w1, a4[i]);
                a4[i] = ffma2(pk2(av.z, av.z), w2, a4[i]);
                a4[i] = ffma2(pk2(av.w, av.w), w3, a4[i]);
            }
        }
        #pragma unroll
        for (int i = 0; i < 8; i++) {
            float lo, hi;
            upk2(a4[i], lo, hi);
            float* o = out + ((size_t)side * 8192 + b0 + r0 + i) * 60 + c2;
            o[0] = lo; o[1] = hi;
        }
    }
}

// ---------------- launch ----------------
extern "C" void kernel_launch(void* const* d_in, const int* in_sizes, int n_in,
                              void* d_out, int out_size) {
    (void)in_sizes; (void)n_in; (void)out_size;
    const float* memb      = (const float*)d_in[0];
    const float* edge_feat = (const float*)d_in[1];
    const float* Wq        = (const float*)d_in[2];
    const float* Wk        = (const float*)d_in[3];
    const float* a         = (const float*)d_in[4];
    const float* Wew       = (const float*)d_in[5];
    const float* Web       = (const float*)d_in[6];
    const float* Wuc       = (const float*)d_in[7];
    const float* Wc1       = (const float*)d_in[8];
    const float* Wc2       = (const float*)d_in[9];
    const int* src_idxs    = (const int*)d_in[10];
    const int* dst_idxs    = (const int*)d_in[11];
    const int* edge_idxs   = (const int*)d_in[12];
    const int* src_nb      = (const int*)d_in[13];
    const int* dst_nb      = (const int*)d_in[14];
    float* out = (float*)d_out;

    setup_small<<<1, 128>>>(Wq, Wk, a, Web, Wuc);
    attend_kernel<<<2048, 256>>>(memb, src_idxs, dst_idxs, src_nb, dst_nb);
    setup_wbig<<<384, 256>>>(Wk, Wew, Wuc);
    cudaFuncSetAttribute(final_kernel, cudaFuncAttributeMaxDynamicSharedMemorySize,
                         FINAL_SMEM_BYTES);
    final_kernel<<<dim3(128, 2), 256, FINAL_SMEM_BYTES>>>(memb, edge_feat, Wuc, Wc1, Wc2,
                                                          src_idxs, dst_idxs, edge_idxs, out);
}